// round 5
// baseline (speedup 1.0000x reference)
#include <cuda_runtime.h>
#include <cuda_bf16.h>
#include <cstdint>

// Problem constants (shapes fixed by the dataset; M taken from in_sizes at runtime)
#define DIM 512
#define MAX_NODES 100000

// Scratch for projected features hp = h @ W (204.8 MB __device__ global —
// the sanctioned allocation-free scratch mechanism)
__device__ float g_hp[(size_t)MAX_NODES * DIM];

// ---------------------------------------------------------------------------
// SGEMM: C[M x 512] = A[M x 512] @ B[512 x 512], fp32.
// 128x128 block tile, BK=16, 256 threads, 8x8 per-thread micro-tile.
// ---------------------------------------------------------------------------
__global__ __launch_bounds__(256) void sgemm_kernel(const float* __restrict__ A,
                                                    const float* __restrict__ B,
                                                    float* __restrict__ C,
                                                    int M) {
    const int K = DIM;
    const int N = DIM;

    __shared__ float As[16][128];   // transposed: As[k][m]
    __shared__ float Bs[16][128];   // Bs[k][n]

    const int tid = threadIdx.x;
    const int bm  = blockIdx.y * 128;
    const int bn  = blockIdx.x * 128;

    const int tr = (tid / 16) * 8;   // row offset within tile
    const int tc = (tid % 16) * 8;   // col offset within tile

    float acc[8][8];
#pragma unroll
    for (int i = 0; i < 8; i++)
#pragma unroll
        for (int j = 0; j < 8; j++) acc[i][j] = 0.0f;

    const int arow = tid >> 2;          // 0..63  (second pass +64)
    const int acol = (tid & 3) * 4;     // 0,4,8,12
    const int brow = tid >> 5;          // 0..7   (second pass +8)
    const int bcol = (tid & 31) * 4;    // 0..124

    for (int k0 = 0; k0 < K; k0 += 16) {
        // A tile (transpose into As[k][m]); zero-fill rows beyond M
#pragma unroll
        for (int p = 0; p < 2; p++) {
            const int r = arow + p * 64;
            float4 a;
            if (bm + r < M) {
                a = *(const float4*)&A[(size_t)(bm + r) * K + k0 + acol];
            } else {
                a = make_float4(0.f, 0.f, 0.f, 0.f);
            }
            As[acol + 0][r] = a.x;
            As[acol + 1][r] = a.y;
            As[acol + 2][r] = a.z;
            As[acol + 3][r] = a.w;
        }
        // B tile (row-major, coalesced)
#pragma unroll
        for (int p = 0; p < 2; p++) {
            const int r = brow + p * 8;
            *(float4*)&Bs[r][bcol] = *(const float4*)&B[(size_t)(k0 + r) * N + bn + bcol];
        }
        __syncthreads();

#pragma unroll
        for (int k = 0; k < 16; k++) {
            float a[8], b[8];
            *(float4*)&a[0] = *(const float4*)&As[k][tr];
            *(float4*)&a[4] = *(const float4*)&As[k][tr + 4];
            *(float4*)&b[0] = *(const float4*)&Bs[k][tc];
            *(float4*)&b[4] = *(const float4*)&Bs[k][tc + 4];
#pragma unroll
            for (int i = 0; i < 8; i++)
#pragma unroll
                for (int j = 0; j < 8; j++)
                    acc[i][j] = fmaf(a[i], b[j], acc[i][j]);
        }
        __syncthreads();
    }

#pragma unroll
    for (int i = 0; i < 8; i++) {
        const int r = bm + tr + i;
        if (r < M) {
            float4 v0 = make_float4(acc[i][0], acc[i][1], acc[i][2], acc[i][3]);
            float4 v1 = make_float4(acc[i][4], acc[i][5], acc[i][6], acc[i][7]);
            *(float4*)&C[(size_t)r * N + bn + tc]     = v0;
            *(float4*)&C[(size_t)r * N + bn + tc + 4] = v1;
        }
    }
}

// ---------------------------------------------------------------------------
// Edge scatter: out[dst[e], :] += g_hp[src[e], :] * ew[e]
// 128 consecutive threads cover one edge (one float4 / thread): ew/src/dst
// loads are warp-uniform broadcasts; the hp gather is a coalesced 2KB row
// read; atomicAdd without return lowers to RED.
// NOTE: src/dst are int32 (JAX x64-disabled downcasts the reference's int64).
// ---------------------------------------------------------------------------
__global__ __launch_bounds__(256) void scatter_kernel(const float* __restrict__ ew,
                                                      const int* __restrict__ src,
                                                      const int* __restrict__ dst,
                                                      float* __restrict__ out,
                                                      int E) {
    const long long idx = (long long)blockIdx.x * blockDim.x + threadIdx.x;
    const long long total = (long long)E * (DIM / 4);
    if (idx >= total) return;

    const int e  = (int)(idx >> 7);    // DIM/4 = 128 float4 per edge
    const int d4 = (int)(idx & 127);

    const float w = ew[e];
    const int   s = src[e];
    const int   t = dst[e];

    const float4 v = *(const float4*)&g_hp[(size_t)s * DIM + (size_t)d4 * 4];
    float* o = out + (size_t)t * DIM + (size_t)d4 * 4;
    atomicAdd(o + 0, v.x * w);
    atomicAdd(o + 1, v.y * w);
    atomicAdd(o + 2, v.z * w);
    atomicAdd(o + 3, v.w * w);
}

// ---------------------------------------------------------------------------
// In-place ReLU
// ---------------------------------------------------------------------------
__global__ __launch_bounds__(256) void relu_kernel(float* __restrict__ out, int n4) {
    const int i = blockIdx.x * blockDim.x + threadIdx.x;
    if (i < n4) {
        float4 v = ((float4*)out)[i];
        v.x = fmaxf(v.x, 0.f);
        v.y = fmaxf(v.y, 0.f);
        v.z = fmaxf(v.z, 0.f);
        v.w = fmaxf(v.w, 0.f);
        ((float4*)out)[i] = v;
    }
}

// ---------------------------------------------------------------------------
// Launch: memset(out) -> GEMM -> scatter -> relu (graph-capturable, no allocs)
// ---------------------------------------------------------------------------
extern "C" void kernel_launch(void* const* d_in, const int* in_sizes, int n_in,
                              void* d_out, int out_size) {
    const float* h   = (const float*)d_in[0];   // [M, 512] fp32
    const float* wgt = (const float*)d_in[1];   // [512, 512] fp32
    const float* ew  = (const float*)d_in[2];   // [E] fp32
    const int*   src = (const int*)d_in[3];     // [E] int32
    const int*   dst = (const int*)d_in[4];     // [E] int32
    float* out = (float*)d_out;                 // [M, 512] fp32

    const int M = in_sizes[0] / DIM;
    const int E = in_sizes[2];

    float* hp_dev = nullptr;
    cudaGetSymbolAddress((void**)&hp_dev, g_hp);

    // 1) zero the (poisoned) output accumulator
    cudaMemsetAsync(d_out, 0, (size_t)out_size * sizeof(float), 0);

    // 2) hp = h @ W
    {
        dim3 grid(DIM / 128, (M + 127) / 128);
        sgemm_kernel<<<grid, 256>>>(h, wgt, hp_dev, M);
    }

    // 3) out[dst] += hp[src] * ew
    {
        const long long total = (long long)E * (DIM / 4);
        const int threads = 256;
        const long long blocks = (total + threads - 1) / threads;
        scatter_kernel<<<(unsigned)blocks, threads>>>(ew, src, dst, out, E);
    }

    // 4) ReLU in place
    {
        const int n4 = out_size / 4;
        relu_kernel<<<(n4 + 255) / 256, 256>>>(out, n4);
    }
}

// round 8
// speedup vs baseline: 1.9785x; 1.9785x over previous
#include <cuda_runtime.h>
#include <cuda_bf16.h>
#include <cstdint>

// Problem constants (dataset-fixed shapes; M/E taken from in_sizes at runtime)
#define DIM 512
#define MAX_NODES 100000
#define MAX_EDGES 1600000

// ---------------------------------------------------------------------------
// __device__ global scratch (the sanctioned allocation-free mechanism)
// ---------------------------------------------------------------------------
__device__ float g_hp[(size_t)MAX_NODES * DIM];   // projected features, 204.8 MB
__device__ int   g_deg[MAX_NODES];                // in-degree histogram
__device__ int   g_rowptr[MAX_NODES + 1];         // CSR row pointers
__device__ int   g_cursor[MAX_NODES];             // fill cursors
__device__ int   g_esrc[MAX_EDGES];               // per-slot source node
__device__ float g_eww[MAX_EDGES];                // per-slot edge weight

// ---------------------------------------------------------------------------
// SGEMM: C[M x 512] = A[M x 512] @ B[512 x 512], fp32.
// 128x128 block tile, BK=16, 256 threads, 8x8 per-thread micro-tile.
// (unchanged from the passing R3 kernel)
// ---------------------------------------------------------------------------
__global__ __launch_bounds__(256) void sgemm_kernel(const float* __restrict__ A,
                                                    const float* __restrict__ B,
                                                    float* __restrict__ C,
                                                    int M) {
    const int K = DIM;
    const int N = DIM;

    __shared__ float As[16][128];   // transposed: As[k][m]
    __shared__ float Bs[16][128];   // Bs[k][n]

    const int tid = threadIdx.x;
    const int bm  = blockIdx.y * 128;
    const int bn  = blockIdx.x * 128;

    const int tr = (tid / 16) * 8;
    const int tc = (tid % 16) * 8;

    float acc[8][8];
#pragma unroll
    for (int i = 0; i < 8; i++)
#pragma unroll
        for (int j = 0; j < 8; j++) acc[i][j] = 0.0f;

    const int arow = tid >> 2;
    const int acol = (tid & 3) * 4;
    const int brow = tid >> 5;
    const int bcol = (tid & 31) * 4;

    for (int k0 = 0; k0 < K; k0 += 16) {
#pragma unroll
        for (int p = 0; p < 2; p++) {
            const int r = arow + p * 64;
            float4 a;
            if (bm + r < M) {
                a = *(const float4*)&A[(size_t)(bm + r) * K + k0 + acol];
            } else {
                a = make_float4(0.f, 0.f, 0.f, 0.f);
            }
            As[acol + 0][r] = a.x;
            As[acol + 1][r] = a.y;
            As[acol + 2][r] = a.z;
            As[acol + 3][r] = a.w;
        }
#pragma unroll
        for (int p = 0; p < 2; p++) {
            const int r = brow + p * 8;
            *(float4*)&Bs[r][bcol] = *(const float4*)&B[(size_t)(k0 + r) * N + bn + bcol];
        }
        __syncthreads();

#pragma unroll
        for (int k = 0; k < 16; k++) {
            float a[8], b[8];
            *(float4*)&a[0] = *(const float4*)&As[k][tr];
            *(float4*)&a[4] = *(const float4*)&As[k][tr + 4];
            *(float4*)&b[0] = *(const float4*)&Bs[k][tc];
            *(float4*)&b[4] = *(const float4*)&Bs[k][tc + 4];
#pragma unroll
            for (int i = 0; i < 8; i++)
#pragma unroll
                for (int j = 0; j < 8; j++)
                    acc[i][j] = fmaf(a[i], b[j], acc[i][j]);
        }
        __syncthreads();
    }

#pragma unroll
    for (int i = 0; i < 8; i++) {
        const int r = bm + tr + i;
        if (r < M) {
            float4 v0 = make_float4(acc[i][0], acc[i][1], acc[i][2], acc[i][3]);
            float4 v1 = make_float4(acc[i][4], acc[i][5], acc[i][6], acc[i][7]);
            *(float4*)&C[(size_t)r * N + bn + tc]     = v0;
            *(float4*)&C[(size_t)r * N + bn + tc + 4] = v1;
        }
    }
}

// ---------------------------------------------------------------------------
// CSR build step 1: in-degree histogram (RED.ADD, spread addresses)
// ---------------------------------------------------------------------------
__global__ __launch_bounds__(256) void degree_kernel(const int* __restrict__ dst, int E) {
    const int e = blockIdx.x * blockDim.x + threadIdx.x;
    if (e < E) atomicAdd(&g_deg[dst[e]], 1);
}

// ---------------------------------------------------------------------------
// CSR build step 2: exclusive scan of g_deg -> g_rowptr (single CTA, 1024 thr)
// Each thread owns a contiguous chunk; block-level Hillis-Steele over the
// 1024 chunk sums; then per-thread sequential prefix write.
// ---------------------------------------------------------------------------
__global__ __launch_bounds__(1024) void scan_kernel(int M) {
    __shared__ int ssum[1024];
    const int tid   = threadIdx.x;
    const int chunk = (M + 1023) / 1024;
    const int begin = tid * chunk;
    const int end   = min(begin + chunk, M);

    int s = 0;
    for (int i = begin; i < end; i++) s += g_deg[i];
    ssum[tid] = s;
    __syncthreads();

    // inclusive Hillis-Steele scan over ssum
    for (int off = 1; off < 1024; off <<= 1) {
        int v = 0;
        if (tid >= off) v = ssum[tid - off];
        __syncthreads();
        ssum[tid] += v;
        __syncthreads();
    }

    int run = (tid == 0) ? 0 : ssum[tid - 1];   // exclusive prefix of this chunk
    for (int i = begin; i < end; i++) {
        g_rowptr[i] = run;
        run += g_deg[i];
    }
    if (tid == 1023) g_rowptr[M] = ssum[1023];
}

// ---------------------------------------------------------------------------
// CSR build step 3: fill per-node contiguous (src, weight) slots
// ---------------------------------------------------------------------------
__global__ __launch_bounds__(256) void fill_kernel(const int* __restrict__ src,
                                                   const int* __restrict__ dst,
                                                   const float* __restrict__ ew,
                                                   int E) {
    const int e = blockIdx.x * blockDim.x + threadIdx.x;
    if (e >= E) return;
    const int t    = dst[e];
    const int pos  = atomicAdd(&g_cursor[t], 1);
    const int slot = g_rowptr[t] + pos;
    g_esrc[slot] = src[e];
    g_eww[slot]  = ew[e];
}

// ---------------------------------------------------------------------------
// Aggregation: out[n,:] = relu( sum_{edges e->n} hp[src_e,:] * w_e )
// One 128-thread CTA per node; each thread owns one float4 lane (4 dims).
// Register accumulation, 2-edge unroll for MLP, fused ReLU, single write.
// Writes EVERY output element (out is poisoned; deg-0 nodes get relu(0)=0).
// ---------------------------------------------------------------------------
__global__ __launch_bounds__(128) void aggregate_kernel(float* __restrict__ out) {
    const int n   = blockIdx.x;
    const int tid = threadIdx.x;                  // 0..127, one float4 each

    const int start = g_rowptr[n];
    const int end   = g_rowptr[n + 1];

    const float4* __restrict__ hp4 = (const float4*)g_hp;

    float4 acc = make_float4(0.f, 0.f, 0.f, 0.f);

    int i = start;
    for (; i + 1 < end; i += 2) {
        const int   s0 = g_esrc[i];
        const int   s1 = g_esrc[i + 1];
        const float w0 = g_eww[i];
        const float w1 = g_eww[i + 1];
        const float4 v0 = hp4[(size_t)s0 * (DIM / 4) + tid];
        const float4 v1 = hp4[(size_t)s1 * (DIM / 4) + tid];
        acc.x += v0.x * w0 + v1.x * w1;
        acc.y += v0.y * w0 + v1.y * w1;
        acc.z += v0.z * w0 + v1.z * w1;
        acc.w += v0.w * w0 + v1.w * w1;
    }
    if (i < end) {
        const int   s0 = g_esrc[i];
        const float w0 = g_eww[i];
        const float4 v0 = hp4[(size_t)s0 * (DIM / 4) + tid];
        acc.x += v0.x * w0;
        acc.y += v0.y * w0;
        acc.z += v0.z * w0;
        acc.w += v0.w * w0;
    }

    acc.x = fmaxf(acc.x, 0.f);
    acc.y = fmaxf(acc.y, 0.f);
    acc.z = fmaxf(acc.z, 0.f);
    acc.w = fmaxf(acc.w, 0.f);
    ((float4*)out)[(size_t)n * (DIM / 4) + tid] = acc;
}

// ---------------------------------------------------------------------------
// Launch: CSR build + GEMM + gather-aggregate (graph-capturable, no allocs)
// ---------------------------------------------------------------------------
extern "C" void kernel_launch(void* const* d_in, const int* in_sizes, int n_in,
                              void* d_out, int out_size) {
    const float* h   = (const float*)d_in[0];   // [M, 512] fp32
    const float* wgt = (const float*)d_in[1];   // [512, 512] fp32
    const float* ew  = (const float*)d_in[2];   // [E] fp32
    const int*   src = (const int*)d_in[3];     // [E] int32
    const int*   dst = (const int*)d_in[4];     // [E] int32
    float* out = (float*)d_out;                 // [M, 512] fp32

    const int M = in_sizes[0] / DIM;
    const int E = in_sizes[2];

    float* hp_dev = nullptr;
    cudaGetSymbolAddress((void**)&hp_dev, g_hp);
    int* deg_dev = nullptr;
    cudaGetSymbolAddress((void**)&deg_dev, g_deg);
    int* cur_dev = nullptr;
    cudaGetSymbolAddress((void**)&cur_dev, g_cursor);

    // --- CSR build ---
    cudaMemsetAsync(deg_dev, 0, (size_t)M * sizeof(int), 0);
    cudaMemsetAsync(cur_dev, 0, (size_t)M * sizeof(int), 0);
    degree_kernel<<<(E + 255) / 256, 256>>>(dst, E);
    scan_kernel<<<1, 1024>>>(M);
    fill_kernel<<<(E + 255) / 256, 256>>>(src, dst, ew, E);

    // --- hp = h @ W ---
    {
        dim3 grid(DIM / 128, (M + 127) / 128);
        sgemm_kernel<<<grid, 256>>>(h, wgt, hp_dev, M);
    }

    // --- out[n] = relu(sum over in-edges of hp[src]*w) ---
    aggregate_kernel<<<M, 128>>>(out);
}

// round 9
// speedup vs baseline: 3.4909x; 1.7644x over previous
#include <cuda_runtime.h>
#include <cuda_bf16.h>
#include <cstdint>

// Problem constants (dataset-fixed shapes; M/E from in_sizes at runtime)
#define DIM 512
#define MAX_NODES 100000
#define MAX_EDGES 1600000

// ---------------------------------------------------------------------------
// __device__ global scratch (sanctioned allocation-free mechanism)
// ---------------------------------------------------------------------------
__device__ float g_hp[(size_t)MAX_NODES * DIM];   // projected features
__device__ int   g_deg[MAX_NODES];
__device__ int   g_rowptr[MAX_NODES + 1];
__device__ int   g_cursor[MAX_NODES];
__device__ int   g_esrc[MAX_EDGES];
__device__ float g_eww[MAX_EDGES];

// ---------------------------------------------------------------------------
// PTX helpers
// ---------------------------------------------------------------------------
__device__ __forceinline__ uint32_t sptr(const void* p) {
    return (uint32_t)__cvta_generic_to_shared(p);
}
__device__ __forceinline__ void ldsm_x4(uint32_t& r0, uint32_t& r1, uint32_t& r2,
                                        uint32_t& r3, uint32_t addr) {
    asm volatile("ldmatrix.sync.aligned.m8n8.x4.shared.b16 {%0,%1,%2,%3}, [%4];"
                 : "=r"(r0), "=r"(r1), "=r"(r2), "=r"(r3) : "r"(addr));
}
__device__ __forceinline__ void ldsm_x2_trans(uint32_t& r0, uint32_t& r1, uint32_t addr) {
    asm volatile("ldmatrix.sync.aligned.m8n8.x2.trans.shared.b16 {%0,%1}, [%2];"
                 : "=r"(r0), "=r"(r1) : "r"(addr));
}
__device__ __forceinline__ void mma_bf16(float* d, const uint32_t* a, const uint32_t* b) {
    asm volatile(
        "mma.sync.aligned.m16n8k16.row.col.f32.bf16.bf16.f32 "
        "{%0,%1,%2,%3}, {%4,%5,%6,%7}, {%8,%9}, {%0,%1,%2,%3};"
        : "+f"(d[0]), "+f"(d[1]), "+f"(d[2]), "+f"(d[3])
        : "r"(a[0]), "r"(a[1]), "r"(a[2]), "r"(a[3]), "r"(b[0]), "r"(b[1]));
}
__device__ __forceinline__ uint32_t pack_bf16x2(__nv_bfloat16 lo, __nv_bfloat16 hi) {
    __nv_bfloat162 t = __halves2bfloat162(lo, hi);
    return *(uint32_t*)&t;
}

// ---------------------------------------------------------------------------
// Tensor-core GEMM: C[M x 512] = A[M x 512] @ B[512 x 512], fp32 in/out.
// bf16 2-term split per operand, 3 mma passes: AhBh + AhBl + AlBh.
// Block tile 128x128x32, 8 warps (4x2), warp tile 32x64.
// ---------------------------------------------------------------------------
#define A_STRIDE 40    // bf16 elems per A smem row (32 + 8 pad), %8==0
#define B_STRIDE 136   // bf16 elems per B smem row (128 + 8 pad), %8==0

__global__ __launch_bounds__(256) void gemm_tc_kernel(const float* __restrict__ A,
                                                      const float* __restrict__ B,
                                                      float* __restrict__ C,
                                                      int M) {
    __shared__ __nv_bfloat16 As_hi[128 * A_STRIDE];   // [m][k]
    __shared__ __nv_bfloat16 As_lo[128 * A_STRIDE];
    __shared__ __nv_bfloat16 Bs_hi[32 * B_STRIDE];    // [k][n]
    __shared__ __nv_bfloat16 Bs_lo[32 * B_STRIDE];

    const int tid  = threadIdx.x;
    const int lane = tid & 31;
    const int wid  = tid >> 5;
    const int warp_m = wid & 3;   // 4 warp-rows of 32
    const int warp_n = wid >> 2;  // 2 warp-cols of 64

    const int bm = blockIdx.y * 128;
    const int bn = blockIdx.x * 128;

    float acc[2][8][4];
#pragma unroll
    for (int i = 0; i < 2; i++)
#pragma unroll
        for (int j = 0; j < 8; j++)
#pragma unroll
            for (int r = 0; r < 4; r++) acc[i][j][r] = 0.0f;

    for (int k0 = 0; k0 < DIM; k0 += 32) {
        // ---- stage A chunk: 128 rows x 32 k (1024 float4, 4 per thread) ----
#pragma unroll
        for (int j = 0; j < 4; j++) {
            const int l   = tid + 256 * j;
            const int row = l >> 3;
            const int c4  = (l & 7) * 4;
            float4 v;
            if (bm + row < M) v = *(const float4*)&A[(size_t)(bm + row) * DIM + k0 + c4];
            else              v = make_float4(0.f, 0.f, 0.f, 0.f);

            float hx = __bfloat162float(__float2bfloat16(v.x));
            float hy = __bfloat162float(__float2bfloat16(v.y));
            float hz = __bfloat162float(__float2bfloat16(v.z));
            float hw = __bfloat162float(__float2bfloat16(v.w));
            uint32_t* ph = (uint32_t*)&As_hi[row * A_STRIDE + c4];
            uint32_t* pl = (uint32_t*)&As_lo[row * A_STRIDE + c4];
            ph[0] = pack_bf16x2(__float2bfloat16(v.x), __float2bfloat16(v.y));
            ph[1] = pack_bf16x2(__float2bfloat16(v.z), __float2bfloat16(v.w));
            pl[0] = pack_bf16x2(__float2bfloat16(v.x - hx), __float2bfloat16(v.y - hy));
            pl[1] = pack_bf16x2(__float2bfloat16(v.z - hz), __float2bfloat16(v.w - hw));
        }
        // ---- stage B chunk: 32 k-rows x 128 n (kept [k][n], coalesced) ----
#pragma unroll
        for (int j = 0; j < 4; j++) {
            const int l    = tid + 256 * j;
            const int krow = l >> 5;
            const int nc   = (l & 31) * 4;
            float4 v = *(const float4*)&B[(size_t)(k0 + krow) * DIM + bn + nc];

            float hx = __bfloat162float(__float2bfloat16(v.x));
            float hy = __bfloat162float(__float2bfloat16(v.y));
            float hz = __bfloat162float(__float2bfloat16(v.z));
            float hw = __bfloat162float(__float2bfloat16(v.w));
            uint32_t* ph = (uint32_t*)&Bs_hi[krow * B_STRIDE + nc];
            uint32_t* pl = (uint32_t*)&Bs_lo[krow * B_STRIDE + nc];
            ph[0] = pack_bf16x2(__float2bfloat16(v.x), __float2bfloat16(v.y));
            ph[1] = pack_bf16x2(__float2bfloat16(v.z), __float2bfloat16(v.w));
            pl[0] = pack_bf16x2(__float2bfloat16(v.x - hx), __float2bfloat16(v.y - hy));
            pl[1] = pack_bf16x2(__float2bfloat16(v.z - hz), __float2bfloat16(v.w - hw));
        }
        __syncthreads();

        // ---- compute: 2 k16 steps ----
#pragma unroll
        for (int ks = 0; ks < 2; ks++) {
            const int kk = ks * 16;

            // A fragments for this warp's 2 m16 tiles (hi and lo)
            uint32_t a_hi[2][4], a_lo[2][4];
#pragma unroll
            for (int mt = 0; mt < 2; mt++) {
                const int row = warp_m * 32 + mt * 16 + (lane & 15);
                const int col = kk + (lane >> 4) * 8;
                const uint32_t off = (uint32_t)(row * A_STRIDE + col) * 2;
                ldsm_x4(a_hi[mt][0], a_hi[mt][1], a_hi[mt][2], a_hi[mt][3],
                        sptr(As_hi) + off);
                ldsm_x4(a_lo[mt][0], a_lo[mt][1], a_lo[mt][2], a_lo[mt][3],
                        sptr(As_lo) + off);
            }

#pragma unroll
            for (int nt = 0; nt < 8; nt++) {
                const int n_base = warp_n * 64 + nt * 8;
                // B-frag via ldmatrix.trans from [k][n] storage
                const int krow = kk + ((lane & 15) >> 3) * 8 + (lane & 7);
                const uint32_t boff = (uint32_t)(krow * B_STRIDE + n_base) * 2;
                uint32_t b_hi[2], b_lo[2];
                ldsm_x2_trans(b_hi[0], b_hi[1], sptr(Bs_hi) + boff);
                ldsm_x2_trans(b_lo[0], b_lo[1], sptr(Bs_lo) + boff);
#pragma unroll
                for (int mt = 0; mt < 2; mt++) {
                    mma_bf16(acc[mt][nt], a_hi[mt], b_hi);   // Ahi @ Bhi
                    mma_bf16(acc[mt][nt], a_hi[mt], b_lo);   // Ahi @ Blo
                    mma_bf16(acc[mt][nt], a_lo[mt], b_hi);   // Alo @ Bhi
                }
            }
        }
        __syncthreads();
    }

    // ---- epilogue: d-frag thread map: rows g=lane/4 (+8), cols 2*(lane%4) ----
#pragma unroll
    for (int mt = 0; mt < 2; mt++) {
#pragma unroll
        for (int nt = 0; nt < 8; nt++) {
            const int row0 = bm + warp_m * 32 + mt * 16 + (lane >> 2);
            const int col  = bn + warp_n * 64 + nt * 8 + (lane & 3) * 2;
            if (row0 < M) {
                float2 v = make_float2(acc[mt][nt][0], acc[mt][nt][1]);
                *(float2*)&C[(size_t)row0 * DIM + col] = v;
            }
            if (row0 + 8 < M) {
                float2 v = make_float2(acc[mt][nt][2], acc[mt][nt][3]);
                *(float2*)&C[(size_t)(row0 + 8) * DIM + col] = v;
            }
        }
    }
}

// ---------------------------------------------------------------------------
// CSR build step 1: in-degree histogram
// ---------------------------------------------------------------------------
__global__ __launch_bounds__(256) void degree_kernel(const int* __restrict__ dst, int E) {
    const int e = blockIdx.x * blockDim.x + threadIdx.x;
    if (e < E) atomicAdd(&g_deg[dst[e]], 1);
}

// ---------------------------------------------------------------------------
// CSR build step 2: exclusive scan (single CTA)
// ---------------------------------------------------------------------------
__global__ __launch_bounds__(1024) void scan_kernel(int M) {
    __shared__ int ssum[1024];
    const int tid   = threadIdx.x;
    const int chunk = (M + 1023) / 1024;
    const int begin = tid * chunk;
    const int end   = min(begin + chunk, M);

    int s = 0;
    for (int i = begin; i < end; i++) s += g_deg[i];
    ssum[tid] = s;
    __syncthreads();

    for (int off = 1; off < 1024; off <<= 1) {
        int v = 0;
        if (tid >= off) v = ssum[tid - off];
        __syncthreads();
        ssum[tid] += v;
        __syncthreads();
    }

    int run = (tid == 0) ? 0 : ssum[tid - 1];
    for (int i = begin; i < end; i++) {
        g_rowptr[i] = run;
        run += g_deg[i];
    }
    if (tid == 1023) g_rowptr[M] = ssum[1023];
}

// ---------------------------------------------------------------------------
// CSR build step 3: fill slots
// ---------------------------------------------------------------------------
__global__ __launch_bounds__(256) void fill_kernel(const int* __restrict__ src,
                                                   const int* __restrict__ dst,
                                                   const float* __restrict__ ew,
                                                   int E) {
    const int e = blockIdx.x * blockDim.x + threadIdx.x;
    if (e >= E) return;
    const int t    = dst[e];
    const int pos  = atomicAdd(&g_cursor[t], 1);
    const int slot = g_rowptr[t] + pos;
    g_esrc[slot] = src[e];
    g_eww[slot]  = ew[e];
}

// ---------------------------------------------------------------------------
// Aggregation: out[n,:] = relu( sum_e hp[src_e,:] * w_e ), one CTA per node
// ---------------------------------------------------------------------------
__global__ __launch_bounds__(128) void aggregate_kernel(float* __restrict__ out) {
    const int n   = blockIdx.x;
    const int tid = threadIdx.x;

    const int start = g_rowptr[n];
    const int end   = g_rowptr[n + 1];

    const float4* __restrict__ hp4 = (const float4*)g_hp;
    float4 acc = make_float4(0.f, 0.f, 0.f, 0.f);

    int i = start;
    for (; i + 1 < end; i += 2) {
        const int   s0 = g_esrc[i];
        const int   s1 = g_esrc[i + 1];
        const float w0 = g_eww[i];
        const float w1 = g_eww[i + 1];
        const float4 v0 = hp4[(size_t)s0 * (DIM / 4) + tid];
        const float4 v1 = hp4[(size_t)s1 * (DIM / 4) + tid];
        acc.x += v0.x * w0 + v1.x * w1;
        acc.y += v0.y * w0 + v1.y * w1;
        acc.z += v0.z * w0 + v1.z * w1;
        acc.w += v0.w * w0 + v1.w * w1;
    }
    if (i < end) {
        const int   s0 = g_esrc[i];
        const float w0 = g_eww[i];
        const float4 v0 = hp4[(size_t)s0 * (DIM / 4) + tid];
        acc.x += v0.x * w0;
        acc.y += v0.y * w0;
        acc.z += v0.z * w0;
        acc.w += v0.w * w0;
    }

    acc.x = fmaxf(acc.x, 0.f);
    acc.y = fmaxf(acc.y, 0.f);
    acc.z = fmaxf(acc.z, 0.f);
    acc.w = fmaxf(acc.w, 0.f);
    ((float4*)out)[(size_t)n * (DIM / 4) + tid] = acc;
}

// ---------------------------------------------------------------------------
// Launch (graph-capturable, no allocs)
// ---------------------------------------------------------------------------
extern "C" void kernel_launch(void* const* d_in, const int* in_sizes, int n_in,
                              void* d_out, int out_size) {
    const float* h   = (const float*)d_in[0];   // [M, 512] fp32
    const float* wgt = (const float*)d_in[1];   // [512, 512] fp32
    const float* ew  = (const float*)d_in[2];   // [E] fp32
    const int*   src = (const int*)d_in[3];     // [E] int32
    const int*   dst = (const int*)d_in[4];     // [E] int32
    float* out = (float*)d_out;                 // [M, 512] fp32

    const int M = in_sizes[0] / DIM;
    const int E = in_sizes[2];

    float* hp_dev = nullptr;
    cudaGetSymbolAddress((void**)&hp_dev, g_hp);
    int* deg_dev = nullptr;
    cudaGetSymbolAddress((void**)&deg_dev, g_deg);
    int* cur_dev = nullptr;
    cudaGetSymbolAddress((void**)&cur_dev, g_cursor);

    // --- CSR build ---
    cudaMemsetAsync(deg_dev, 0, (size_t)M * sizeof(int), 0);
    cudaMemsetAsync(cur_dev, 0, (size_t)M * sizeof(int), 0);
    degree_kernel<<<(E + 255) / 256, 256>>>(dst, E);
    scan_kernel<<<1, 1024>>>(M);
    fill_kernel<<<(E + 255) / 256, 256>>>(src, dst, ew, E);

    // --- hp = h @ W (tensor cores, bf16 split) ---
    {
        dim3 grid(DIM / 128, (M + 127) / 128);
        gemm_tc_kernel<<<grid, 256>>>(h, wgt, hp_dev, M);
    }

    // --- out[n] = relu(sum over in-edges of hp[src]*w) ---
    aggregate_kernel<<<M, 128>>>(out);
}

// round 15
// speedup vs baseline: 3.5434x; 1.0150x over previous
#include <cuda_runtime.h>
#include <cuda_bf16.h>
#include <cstdint>

// Problem constants (dataset-fixed shapes; M/E from in_sizes at runtime)
#define DIM 512
#define MAX_NODES 100000
#define MAX_EDGES 1600000

// ---------------------------------------------------------------------------
// __device__ global scratch (sanctioned allocation-free mechanism)
// ---------------------------------------------------------------------------
__device__ float g_hp[(size_t)MAX_NODES * DIM];          // projected features
__device__ __nv_bfloat16 g_a_hi[(size_t)MAX_NODES * DIM]; // A split, [m][k]
__device__ __nv_bfloat16 g_a_lo[(size_t)MAX_NODES * DIM];
__device__ __nv_bfloat16 g_wT_hi[DIM * DIM];             // W^T split, [n][k]
__device__ __nv_bfloat16 g_wT_lo[DIM * DIM];
__device__ int   g_deg[MAX_NODES];
__device__ int   g_rowptr[MAX_NODES + 1];
__device__ int   g_cursor[MAX_NODES];
__device__ int   g_esrc[MAX_EDGES];
__device__ float g_eww[MAX_EDGES];

// ---------------------------------------------------------------------------
// PTX helpers (sm_103 baseline features only: mma.sync / ldmatrix / cp.async)
// ---------------------------------------------------------------------------
__device__ __forceinline__ uint32_t smem_u32(const void* p) {
    return (uint32_t)__cvta_generic_to_shared(p);
}
__device__ __forceinline__ void ldsm_x4(uint32_t& r0, uint32_t& r1, uint32_t& r2,
                                        uint32_t& r3, uint32_t addr) {
    asm volatile("ldmatrix.sync.aligned.m8n8.x4.shared.b16 {%0,%1,%2,%3}, [%4];"
                 : "=r"(r0), "=r"(r1), "=r"(r2), "=r"(r3) : "r"(addr));
}
__device__ __forceinline__ void ldsm_x2(uint32_t& r0, uint32_t& r1, uint32_t addr) {
    asm volatile("ldmatrix.sync.aligned.m8n8.x2.shared.b16 {%0,%1}, [%2];"
                 : "=r"(r0), "=r"(r1) : "r"(addr));
}
__device__ __forceinline__ void mma_bf16(float* d, const uint32_t* a, const uint32_t* b) {
    asm volatile(
        "mma.sync.aligned.m16n8k16.row.col.f32.bf16.bf16.f32 "
        "{%0,%1,%2,%3}, {%4,%5,%6,%7}, {%8,%9}, {%0,%1,%2,%3};"
        : "+f"(d[0]), "+f"(d[1]), "+f"(d[2]), "+f"(d[3])
        : "r"(a[0]), "r"(a[1]), "r"(a[2]), "r"(a[3]), "r"(b[0]), "r"(b[1]));
}
__device__ __forceinline__ void cp_async16(uint32_t dst, const void* src, uint32_t src_size) {
    asm volatile("cp.async.cg.shared.global [%0], [%1], 16, %2;"
                 :: "r"(dst), "l"(src), "r"(src_size) : "memory");
}
#define CP_COMMIT() asm volatile("cp.async.commit_group;" ::: "memory")
#define CP_WAIT1()  asm volatile("cp.async.wait_group 1;" ::: "memory")
#define CP_WAIT0()  asm volatile("cp.async.wait_group 0;" ::: "memory")

__device__ __forceinline__ uint32_t pack_bf16x2(__nv_bfloat16 a, __nv_bfloat16 b) {
    __nv_bfloat162 t = __halves2bfloat162(a, b);
    return *(uint32_t*)&t;
}

// ---------------------------------------------------------------------------
// A pre-split: g_a_hi/lo[m][k] = bf16 hi/lo split of A (one streaming pass)
// ---------------------------------------------------------------------------
__global__ __launch_bounds__(256) void split_a_kernel(const float* __restrict__ A,
                                                      long long total4) {
    const long long stride = (long long)gridDim.x * blockDim.x;
    uint2* __restrict__ hi4 = (uint2*)g_a_hi;
    uint2* __restrict__ lo4 = (uint2*)g_a_lo;
    for (long long i = (long long)blockIdx.x * blockDim.x + threadIdx.x;
         i < total4; i += stride) {
        const float4 v = ((const float4*)A)[i];
        const __nv_bfloat16 hx = __float2bfloat16(v.x);
        const __nv_bfloat16 hy = __float2bfloat16(v.y);
        const __nv_bfloat16 hz = __float2bfloat16(v.z);
        const __nv_bfloat16 hw = __float2bfloat16(v.w);
        hi4[i] = make_uint2(pack_bf16x2(hx, hy), pack_bf16x2(hz, hw));
        lo4[i] = make_uint2(
            pack_bf16x2(__float2bfloat16(v.x - __bfloat162float(hx)),
                        __float2bfloat16(v.y - __bfloat162float(hy))),
            pack_bf16x2(__float2bfloat16(v.z - __bfloat162float(hz)),
                        __float2bfloat16(v.w - __bfloat162float(hw))));
    }
}

// ---------------------------------------------------------------------------
// W pre-transpose + bf16 hi/lo split: g_wT_*[n][k] = split(W[k][n])
// ---------------------------------------------------------------------------
__global__ __launch_bounds__(256) void transpose_w_kernel(const float* __restrict__ W) {
    __shared__ float tile[32][33];
    const int tx  = threadIdx.x & 31;
    const int ty8 = threadIdx.x >> 5;
    const int bk  = blockIdx.y * 32;
    const int bn  = blockIdx.x * 32;
#pragma unroll
    for (int j = 0; j < 32; j += 8)
        tile[ty8 + j][tx] = W[(size_t)(bk + ty8 + j) * DIM + bn + tx];
    __syncthreads();
#pragma unroll
    for (int j = 0; j < 32; j += 8) {
        const int n = bn + ty8 + j;
        const int k = bk + tx;
        const float v = tile[tx][ty8 + j];
        const __nv_bfloat16 hi = __float2bfloat16(v);
        g_wT_hi[(size_t)n * DIM + k] = hi;
        g_wT_lo[(size_t)n * DIM + k] = __float2bfloat16(v - __bfloat162float(hi));
    }
}

// ---------------------------------------------------------------------------
// Tensor-core GEMM (mma.sync bf16, 3-pass split: AhBh + AhBl + AlBh).
// Block 128x128, k-chunk 64, 8 warps (4x2), warp tile 32x64.
// cp.async double-buffered smem; operands pre-split in global (no hot-loop cvt).
// smem layout per buffer (64KB): A_hi 16K | A_lo 16K | B_hi 16K | B_lo 16K.
// Rows are 128B (64 bf16); SW128 XOR swizzle seg' = seg ^ (row&7).
// ---------------------------------------------------------------------------
#define BUF_BYTES 65536
#define A_HI_OFF  0
#define A_LO_OFF  16384
#define B_HI_OFF  32768
#define B_LO_OFF  49152
#define GEMM_SMEM (2 * BUF_BYTES)

__global__ __launch_bounds__(256, 1) void gemm_tc_kernel(float* __restrict__ C, int M) {
    extern __shared__ char smem[];
    const uint32_t sbase = smem_u32(smem);
    const int tid  = threadIdx.x;
    const int lane = tid & 31;
    const int wid  = tid >> 5;
    const int warp_m = wid & 3;   // 4 warp-rows of 32
    const int warp_n = wid >> 2;  // 2 warp-cols of 64

    const int bm = blockIdx.y * 128;
    const int bn = blockIdx.x * 128;

    float acc[2][8][4];
#pragma unroll
    for (int i = 0; i < 2; i++)
#pragma unroll
        for (int j = 0; j < 8; j++)
#pragma unroll
            for (int r = 0; r < 4; r++) acc[i][j][r] = 0.0f;

    // ---- stage chunk c into buffer b: 4096 16B cp.asyncs, 16 per thread ----
    auto stage = [&](int c, int b) {
        const int k0 = c * 64;
        const uint32_t bufbase = sbase + b * BUF_BYTES;
#pragma unroll
        for (int j = 0; j < 16; j++) {
            const int l   = tid + 256 * j;
            const int mat = l >> 10;          // 0 A_hi, 1 A_lo, 2 B_hi, 3 B_lo
            const int i   = l & 1023;
            const int row = i >> 3;
            const int seg = i & 7;
            const uint32_t dst = bufbase + (uint32_t)mat * 16384 +
                                 (uint32_t)(row * 128 + ((seg ^ (row & 7)) * 16));
            const __nv_bfloat16* srcs[4] = {g_a_hi, g_a_lo, g_wT_hi, g_wT_lo};
            const __nv_bfloat16* base = srcs[mat];
            const int grow = (mat < 2) ? (bm + row) : (bn + row);
            const bool valid = (mat >= 2) || (grow < M);
            const void* src = base + (size_t)grow * DIM + k0 + seg * 8;
            // out-of-range A rows: keep gaddr in-bounds, zero-fill via src_size=0
            cp_async16(dst, valid ? src : (const void*)base, valid ? 16u : 0u);
        }
        CP_COMMIT();
    };

    stage(0, 0);

    for (int c = 0; c < 8; c++) {
        const int b = c & 1;
        if (c + 1 < 8) {
            stage(c + 1, (c + 1) & 1);
            CP_WAIT1();
        } else {
            CP_WAIT0();
        }
        __syncthreads();

        const uint32_t aHi = sbase + b * BUF_BYTES + A_HI_OFF;
        const uint32_t aLo = sbase + b * BUF_BYTES + A_LO_OFF;
        const uint32_t bHi = sbase + b * BUF_BYTES + B_HI_OFF;
        const uint32_t bLo = sbase + b * BUF_BYTES + B_LO_OFF;

#pragma unroll
        for (int ks = 0; ks < 4; ks++) {
            const int kk = ks * 16;
            // A fragments: row = m, seg = kk/8 + (lane>>4)
            uint32_t a_hi[2][4], a_lo[2][4];
#pragma unroll
            for (int mt = 0; mt < 2; mt++) {
                const int row = warp_m * 32 + mt * 16 + (lane & 15);
                const int seg = (kk >> 3) + (lane >> 4);
                const uint32_t off =
                    (uint32_t)(row * 128 + ((seg ^ (row & 7)) * 16));
                ldsm_x4(a_hi[mt][0], a_hi[mt][1], a_hi[mt][2], a_hi[mt][3], aHi + off);
                ldsm_x4(a_lo[mt][0], a_lo[mt][1], a_lo[mt][2], a_lo[mt][3], aLo + off);
            }
#pragma unroll
            for (int nt = 0; nt < 8; nt++) {
                // B fragment (non-trans x2 from [n][k]): lanes 0-7 -> rows n0..7
                // seg kk/8; lanes 8-15 -> seg kk/8+1
                const int row = warp_n * 64 + nt * 8 + (lane & 7);
                const int seg = (kk >> 3) + ((lane >> 3) & 1);
                const uint32_t off =
                    (uint32_t)(row * 128 + ((seg ^ (row & 7)) * 16));
                uint32_t b_hi[2], b_lo[2];
                ldsm_x2(b_hi[0], b_hi[1], bHi + off);
                ldsm_x2(b_lo[0], b_lo[1], bLo + off);
#pragma unroll
                for (int mt = 0; mt < 2; mt++) {
                    mma_bf16(acc[mt][nt], a_hi[mt], b_hi);   // Ahi @ Bhi
                    mma_bf16(acc[mt][nt], a_hi[mt], b_lo);   // Ahi @ Blo
                    mma_bf16(acc[mt][nt], a_lo[mt], b_hi);   // Alo @ Bhi
                }
            }
        }
        __syncthreads();
    }

    // ---- epilogue: d-frag rows lane/4 (+8), cols 2*(lane%4) ----
#pragma unroll
    for (int mt = 0; mt < 2; mt++) {
#pragma unroll
        for (int nt = 0; nt < 8; nt++) {
            const int row0 = bm + warp_m * 32 + mt * 16 + (lane >> 2);
            const int col  = bn + warp_n * 64 + nt * 8 + (lane & 3) * 2;
            if (row0 < M) {
                *(float2*)&C[(size_t)row0 * DIM + col] =
                    make_float2(acc[mt][nt][0], acc[mt][nt][1]);
            }
            if (row0 + 8 < M) {
                *(float2*)&C[(size_t)(row0 + 8) * DIM + col] =
                    make_float2(acc[mt][nt][2], acc[mt][nt][3]);
            }
        }
    }
}

// ---------------------------------------------------------------------------
// CSR build step 1: in-degree histogram
// ---------------------------------------------------------------------------
__global__ __launch_bounds__(256) void degree_kernel(const int* __restrict__ dst, int E) {
    const int e = blockIdx.x * blockDim.x + threadIdx.x;
    if (e < E) atomicAdd(&g_deg[dst[e]], 1);
}

// ---------------------------------------------------------------------------
// CSR build step 2: exclusive scan (single CTA)
// ---------------------------------------------------------------------------
__global__ __launch_bounds__(1024) void scan_kernel(int M) {
    __shared__ int ssum[1024];
    const int tid   = threadIdx.x;
    const int chunk = (M + 1023) / 1024;
    const int begin = tid * chunk;
    const int end   = min(begin + chunk, M);

    int s = 0;
    for (int i = begin; i < end; i++) s += g_deg[i];
    ssum[tid] = s;
    __syncthreads();

    for (int off = 1; off < 1024; off <<= 1) {
        int v = 0;
        if (tid >= off) v = ssum[tid - off];
        __syncthreads();
        ssum[tid] += v;
        __syncthreads();
    }

    int run = (tid == 0) ? 0 : ssum[tid - 1];
    for (int i = begin; i < end; i++) {
        g_rowptr[i] = run;
        run += g_deg[i];
    }
    if (tid == 1023) g_rowptr[M] = ssum[1023];
}

// ---------------------------------------------------------------------------
// CSR build step 3: fill slots
// ---------------------------------------------------------------------------
__global__ __launch_bounds__(256) void fill_kernel(const int* __restrict__ src,
                                                   const int* __restrict__ dst,
                                                   const float* __restrict__ ew,
                                                   int E) {
    const int e = blockIdx.x * blockDim.x + threadIdx.x;
    if (e >= E) return;
    const int t    = dst[e];
    const int pos  = atomicAdd(&g_cursor[t], 1);
    const int slot = g_rowptr[t] + pos;
    g_esrc[slot] = src[e];
    g_eww[slot]  = ew[e];
}

// ---------------------------------------------------------------------------
// Aggregation: out[n,:] = relu( sum_e hp[src_e,:] * w_e ), one CTA per node
// ---------------------------------------------------------------------------
__global__ __launch_bounds__(128) void aggregate_kernel(float* __restrict__ out) {
    const int n   = blockIdx.x;
    const int tid = threadIdx.x;

    const int start = g_rowptr[n];
    const int end   = g_rowptr[n + 1];

    const float4* __restrict__ hp4 = (const float4*)g_hp;
    float4 acc = make_float4(0.f, 0.f, 0.f, 0.f);

    int i = start;
    for (; i + 1 < end; i += 2) {
        const int   s0 = g_esrc[i];
        const int   s1 = g_esrc[i + 1];
        const float w0 = g_eww[i];
        const float w1 = g_eww[i + 1];
        const float4 v0 = hp4[(size_t)s0 * (DIM / 4) + tid];
        const float4 v1 = hp4[(size_t)s1 * (DIM / 4) + tid];
        acc.x += v0.x * w0 + v1.x * w1;
        acc.y += v0.y * w0 + v1.y * w1;
        acc.z += v0.z * w0 + v1.z * w1;
        acc.w += v0.w * w0 + v1.w * w1;
    }
    if (i < end) {
        const int   s0 = g_esrc[i];
        const float w0 = g_eww[i];
        const float4 v0 = hp4[(size_t)s0 * (DIM / 4) + tid];
        acc.x += v0.x * w0;
        acc.y += v0.y * w0;
        acc.z += v0.z * w0;
        acc.w += v0.w * w0;
    }

    acc.x = fmaxf(acc.x, 0.f);
    acc.y = fmaxf(acc.y, 0.f);
    acc.z = fmaxf(acc.z, 0.f);
    acc.w = fmaxf(acc.w, 0.f);
    ((float4*)out)[(size_t)n * (DIM / 4) + tid] = acc;
}

// ---------------------------------------------------------------------------
// Launch (graph-capturable, no allocs)
// ---------------------------------------------------------------------------
extern "C" void kernel_launch(void* const* d_in, const int* in_sizes, int n_in,
                              void* d_out, int out_size) {
    const float* h   = (const float*)d_in[0];   // [M, 512] fp32
    const float* wgt = (const float*)d_in[1];   // [512, 512] fp32
    const float* ew  = (const float*)d_in[2];   // [E] fp32
    const int*   src = (const int*)d_in[3];     // [E] int32
    const int*   dst = (const int*)d_in[4];     // [E] int32
    float* out = (float*)d_out;                 // [M, 512] fp32

    const int M = in_sizes[0] / DIM;
    const int E = in_sizes[2];

    float* hp_dev = nullptr;
    cudaGetSymbolAddress((void**)&hp_dev, g_hp);
    int* deg_dev = nullptr;
    cudaGetSymbolAddress((void**)&deg_dev, g_deg);
    int* cur_dev = nullptr;
    cudaGetSymbolAddress((void**)&cur_dev, g_cursor);

    cudaFuncSetAttribute(gemm_tc_kernel,
                         cudaFuncAttributeMaxDynamicSharedMemorySize, GEMM_SMEM);

    // --- CSR build ---
    cudaMemsetAsync(deg_dev, 0, (size_t)M * sizeof(int), 0);
    cudaMemsetAsync(cur_dev, 0, (size_t)M * sizeof(int), 0);
    degree_kernel<<<(E + 255) / 256, 256>>>(dst, E);
    scan_kernel<<<1, 1024>>>(M);
    fill_kernel<<<(E + 255) / 256, 256>>>(src, dst, ew, E);

    // --- operand pre-split (A once, W transposed+split once) ---
    split_a_kernel<<<592, 256>>>(h, (long long)M * (DIM / 4));
    {
        dim3 grid(DIM / 32, DIM / 32);
        transpose_w_kernel<<<grid, 256>>>(wgt);
    }

    // --- hp = h @ W (mma.sync bf16 3-pass, cp.async double-buffered) ---
    {
        dim3 grid(DIM / 128, (M + 127) / 128);
        gemm_tc_kernel<<<grid, 256, GEMM_SMEM>>>(hp_dev, M);
    }

    // --- out[n] = relu(sum over in-edges of hp[src]*w) ---
    aggregate_kernel<<<M, 128>>>(out);
}